// round 14
// baseline (speedup 1.0000x reference)
#include <cuda_runtime.h>
#include <cuda_bf16.h>
#include <math.h>
#include <stdint.h>
#include <string.h>

#define N_NODES 50000
#define E_EDGES 800000
#define E_TOT   850000   // E + N self loops
#define IN_DIM  1280
#define HID     256
#define NHEAD   4
#define DHEAD   64

// ---------------- scratch (device globals: no allocation allowed) ----------------
__device__ float g_h[N_NODES * HID];
__device__ float g_xl[N_NODES * HID];
__device__ float g_xr[N_NODES * HID];
__device__ float g_logits[E_TOT * NHEAD];     // deg>SCAP fallback logit staging

// pre-split bf16 h for layer GEMMs
__device__ __nv_bfloat16 g_hhi[N_NODES * HID];
__device__ __nv_bfloat16 g_hlo[N_NODES * HID];

// CSR (in-edges per destination node)
__device__ int g_cnt[N_NODES];
__device__ int g_off[N_NODES + 1];
__device__ int g_cur[N_NODES];
__device__ int g_eid[E_TOT];
__device__ int g_srcs[E_TOT];

// split weights, transposed to [N_out][3*K] bf16, role triplets per 8-k block:
// roles (B side): block 3b+0 = hi, 3b+1 = hi, 3b+2 = lo
__device__ __nv_bfloat16 g_encT[HID * IN_DIM * 3];
__device__ __nv_bfloat16 g_WT[2][512 * HID * 3];   // per layer: [Wl | Wr] merged

// ---------------- PTX helpers ----------------
__device__ __forceinline__ uint32_t smem_u32(const void* p) {
    uint32_t a;
    asm("{ .reg .u64 t; cvta.to.shared.u64 t, %1; cvt.u32.u64 %0, t; }" : "=r"(a) : "l"(p));
    return a;
}
__device__ __forceinline__ void ldsm_x4(uint32_t* r, uint32_t addr) {
    asm volatile("ldmatrix.sync.aligned.m8n8.x4.shared.b16 {%0,%1,%2,%3}, [%4];"
                 : "=r"(r[0]), "=r"(r[1]), "=r"(r[2]), "=r"(r[3]) : "r"(addr));
}
__device__ __forceinline__ void mma16816(float* c, const uint32_t* a, const uint32_t* b) {
    asm volatile("mma.sync.aligned.m16n8k16.row.col.f32.bf16.bf16.f32 "
                 "{%0,%1,%2,%3}, {%4,%5,%6,%7}, {%8,%9}, {%0,%1,%2,%3};"
                 : "+f"(c[0]), "+f"(c[1]), "+f"(c[2]), "+f"(c[3])
                 : "r"(a[0]), "r"(a[1]), "r"(a[2]), "r"(a[3]), "r"(b[0]), "r"(b[1]));
}
__device__ __forceinline__ void cp_async16(uint32_t dst, const void* src, int srcBytes) {
    asm volatile("cp.async.cg.shared.global [%0], [%1], 16, %2;"
                 :: "r"(dst), "l"(src), "r"(srcBytes) : "memory");
}
#define CP_COMMIT() asm volatile("cp.async.commit_group;" ::: "memory")
#define CP_WAIT0()  asm volatile("cp.async.wait_group 0;" ::: "memory")

// ============ encoder GEMM: C[M,256] = A[M,K](fp32) @ B'[256,3K]^T + bias =============
// 128 threads, 4 warps, CTA tile 128x128, warp tile 64x64, BK=32 register double-buffer
// with on-the-fly fp32 -> (hi,lo,hi) bf16 split. Also writes bf16 hi/lo split of C.
__global__ void __launch_bounds__(128, 2)
gemm_enc(const float* __restrict__ A, const __nv_bfloat16* __restrict__ B,
         const float* __restrict__ bias, float* __restrict__ C,
         __nv_bfloat16* __restrict__ Chi, __nv_bfloat16* __restrict__ Clo,
         int M, int K)
{
    const int K2 = 3 * K;
    const int nCh = K2 >> 5;
    __shared__ __align__(16) char smbuf[32768];   // 2 x (A 8KB + B 8KB)

    const int tid  = threadIdx.x;
    const int lane = tid & 31;
    const int wid  = tid >> 5;
    const int mw   = wid & 1;       // 2 m-warps
    const int nw   = wid >> 1;      // 2 n-warps
    const int rowBase = blockIdx.y * 128;
    const int colBase = blockIdx.x * 128;

    float acc[4][8][4];
#pragma unroll
    for (int i = 0; i < 4; i++)
#pragma unroll
        for (int j = 0; j < 8; j++)
#pragma unroll
            for (int k = 0; k < 4; k++) acc[i][j][k] = 0.f;

    uint4 aCvt[4], bReg[4];

    auto ldA = [&](int ch) {
#pragma unroll
        for (int i = 0; i < 4; i++) {
            int id = i * 128 + tid;
            int m = id >> 2, c = id & 3;
            int kb = ch * 4 + c;
            int b3 = kb / 3;
            int role = kb - 3 * b3;
            int rg = rowBase + m;
            float4 v0, v1;
            if (rg < M) {
                const float4* p = (const float4*)(A + (size_t)rg * K + (b3 << 3));
                v0 = p[0]; v1 = p[1];
            } else {
                v0 = make_float4(0.f, 0.f, 0.f, 0.f); v1 = v0;
            }
            float f[8] = {v0.x, v0.y, v0.z, v0.w, v1.x, v1.y, v1.z, v1.w};
            uint32_t w[4];
#pragma unroll
            for (int j = 0; j < 4; j++) {
                float x0 = f[2 * j], x1 = f[2 * j + 1];
                __nv_bfloat162 hp = __floats2bfloat162_rn(x0, x1);
                __nv_bfloat162 ep = hp;
                if (role == 1) {
                    ep = __floats2bfloat162_rn(x0 - __low2float(hp), x1 - __high2float(hp));
                }
                memcpy(&w[j], &ep, 4);
            }
            aCvt[i] = make_uint4(w[0], w[1], w[2], w[3]);
        }
    };
    auto ldB = [&](int ch) {
#pragma unroll
        for (int i = 0; i < 4; i++) {
            int id = i * 128 + tid;
            int n = id >> 2, c = id & 3;
            bReg[i] = *(const uint4*)(B + (size_t)(colBase + n) * K2 + (ch << 5) + (c << 3));
        }
    };
    auto sts = [&](int buf) {
        char* sa = smbuf + buf * 16384;
        char* sb = sa + 8192;
#pragma unroll
        for (int i = 0; i < 4; i++) {
            int id = i * 128 + tid;
            int m = id >> 2, c = id & 3;
            uint32_t off = m * 64 + ((c ^ ((m >> 1) & 3)) << 4);
            *(uint4*)(sa + off) = aCvt[i];
            *(uint4*)(sb + off) = bReg[i];
        }
    };

    ldA(0); ldB(0);
    for (int ch = 0; ch < nCh; ch++) {
        sts(ch & 1);
        __syncthreads();
        if (ch + 1 < nCh) { ldA(ch + 1); ldB(ch + 1); }

        uint32_t sA = smem_u32(smbuf + (ch & 1) * 16384);
        uint32_t sB = sA + 8192;
#pragma unroll
        for (int ks = 0; ks < 2; ks++) {
            uint32_t af[4][4], bf[4][4];
            int g = lane >> 3;
#pragma unroll
            for (int mt = 0; mt < 4; mt++) {
                int r = mw * 64 + mt * 16 + ((g & 1) << 3) + (lane & 7);
                int kb = ks * 2 + (g >> 1);
                ldsm_x4(af[mt], sA + r * 64 + ((kb ^ ((r >> 1) & 3)) << 4));
            }
#pragma unroll
            for (int p = 0; p < 4; p++) {
                int r = nw * 64 + p * 16 + (((g >> 1) & 1) << 3) + (lane & 7);
                int kb = ks * 2 + (g & 1);
                ldsm_x4(bf[p], sB + r * 64 + ((kb ^ ((r >> 1) & 3)) << 4));
            }
#pragma unroll
            for (int mt = 0; mt < 4; mt++)
#pragma unroll
                for (int nt = 0; nt < 8; nt++)
                    mma16816(acc[mt][nt], af[mt], &bf[nt >> 1][(nt & 1) * 2]);
        }
    }

#pragma unroll
    for (int mt = 0; mt < 4; mt++) {
        int m0 = rowBase + mw * 64 + mt * 16 + (lane >> 2);
#pragma unroll
        for (int half = 0; half < 2; half++) {
            int rg = m0 + half * 8;
            if (rg < M) {
                float* cp = C + (size_t)rg * 256;
#pragma unroll
                for (int nt = 0; nt < 8; nt++) {
                    int n0 = colBase + nw * 64 + nt * 8 + (lane & 3) * 2;
                    float2 o;
                    o.x = acc[mt][nt][half * 2 + 0] + bias[n0];
                    o.y = acc[mt][nt][half * 2 + 1] + bias[n0 + 1];
                    *(float2*)(cp + n0) = o;
                    __nv_bfloat162 hb = __floats2bfloat162_rn(o.x, o.y);
                    __nv_bfloat162 lb = __floats2bfloat162_rn(o.x - __low2float(hb),
                                                              o.y - __high2float(hb));
                    *(__nv_bfloat162*)(Chi + (size_t)rg * 256 + n0) = hb;
                    *(__nv_bfloat162*)(Clo + (size_t)rg * 256 + n0) = lb;
                }
            }
        }
    }
}

// ============ layer GEMM: BK=64, 2-stage cp.async, full SW128 swizzle ================
// C[M,512] = h @ [Wl|Wr]^T + bias. 128 threads, 4 warps, CTA 128x128, warp 64x64.
// One __syncthreads + one wait_group per 128 MMAs (4 k16-steps per 64-K chunk).
#define STAGE_BYTES 32768   // A 16KB + B 16KB (128-byte rows)
__global__ void __launch_bounds__(128, 2)
gemm_tc(const __nv_bfloat16* __restrict__ Ahi, const __nv_bfloat16* __restrict__ Alo,
        const __nv_bfloat16* __restrict__ B,
        const float* __restrict__ biasL, const float* __restrict__ biasR,
        float* __restrict__ Cl, float* __restrict__ Cr,
        int M, int K)
{
    const int K2 = 3 * K;          // bf16 elems along K'
    const int nCh = K2 >> 6;       // 64-elem (128-byte) chunks
    extern __shared__ __align__(16) char smbuf[];   // 2 * 32KB
    const uint32_t smbase = smem_u32(smbuf);

    const int tid  = threadIdx.x;
    const int lane = tid & 31;
    const int wid  = tid >> 5;
    const int mw   = wid & 1;
    const int nw   = wid >> 1;
    const int rowBase = blockIdx.y * 128;
    const int colBase = blockIdx.x * 128;

    float acc[4][8][4];
#pragma unroll
    for (int i = 0; i < 4; i++)
#pragma unroll
        for (int j = 0; j < 8; j++)
#pragma unroll
            for (int k = 0; k < 4; k++) acc[i][j][k] = 0.f;

    auto issue = [&](int ch) {
        if (ch < nCh) {
            uint32_t sa = smbase + (ch & 1) * STAGE_BYTES;
            uint32_t sb = sa + 16384;
            // A tile: 128 rows x 128B = 1024 16B-chunks; 8 per thread
#pragma unroll
            for (int i = 0; i < 8; i++) {
                int id = i * 128 + tid;
                int m = id >> 3, c = id & 7;
                int kb = ch * 8 + c;              // global 16B-chunk along K'
                int b3 = kb / 3;
                int role = kb - 3 * b3;
                int rg = rowBase + m;
                int ok = (rg < M);
                const __nv_bfloat16* src = ((role == 1) ? Alo : Ahi)
                                         + (size_t)(ok ? rg : 0) * K + (b3 << 3);
                uint32_t off = m * 128 + ((c ^ (m & 7)) << 4);
                cp_async16(sa + off, src, ok ? 16 : 0);
            }
            // B tile: 128 rows x 128B
#pragma unroll
            for (int i = 0; i < 8; i++) {
                int id = i * 128 + tid;
                int n = id >> 3, c = id & 7;
                const __nv_bfloat16* src = B + (size_t)(colBase + n) * K2 + (ch << 6) + (c << 3);
                uint32_t off = n * 128 + ((c ^ (n & 7)) << 4);
                cp_async16(sb + off, src, 16);
            }
        }
        CP_COMMIT();
    };

    issue(0);
    for (int ch = 0; ch < nCh; ch++) {
        CP_WAIT0();
        __syncthreads();
        issue(ch + 1);

        uint32_t sA = smbase + (ch & 1) * STAGE_BYTES;
        uint32_t sB = sA + 16384;
#pragma unroll
        for (int ks = 0; ks < 4; ks++) {
            uint32_t af[4][4], bf[4][4];
            int g = lane >> 3;
#pragma unroll
            for (int mt = 0; mt < 4; mt++) {
                int r = mw * 64 + mt * 16 + ((g & 1) << 3) + (lane & 7);
                int kb = ks * 2 + (g >> 1);
                ldsm_x4(af[mt], sA + r * 128 + ((kb ^ (r & 7)) << 4));
            }
#pragma unroll
            for (int p = 0; p < 4; p++) {
                int r = nw * 64 + p * 16 + (((g >> 1) & 1) << 3) + (lane & 7);
                int kb = ks * 2 + (g & 1);
                ldsm_x4(bf[p], sB + r * 128 + ((kb ^ (r & 7)) << 4));
            }
#pragma unroll
            for (int mt = 0; mt < 4; mt++)
#pragma unroll
                for (int nt = 0; nt < 8; nt++)
                    mma16816(acc[mt][nt], af[mt], &bf[nt >> 1][(nt & 1) * 2]);
        }
    }

    float* Cout = (colBase < 256) ? Cl : Cr;
    const float* bias = (colBase < 256) ? biasL : biasR;
    const int cb = colBase & 255;

#pragma unroll
    for (int mt = 0; mt < 4; mt++) {
        int m0 = rowBase + mw * 64 + mt * 16 + (lane >> 2);
#pragma unroll
        for (int half = 0; half < 2; half++) {
            int rg = m0 + half * 8;
            if (rg < M) {
                float* cp = Cout + (size_t)rg * 256;
#pragma unroll
                for (int nt = 0; nt < 8; nt++) {
                    int n0 = cb + nw * 64 + nt * 8 + (lane & 3) * 2;
                    float2 o;
                    o.x = acc[mt][nt][half * 2 + 0] + bias[n0];
                    o.y = acc[mt][nt][half * 2 + 1] + bias[n0 + 1];
                    *(float2*)(cp + n0) = o;
                }
            }
        }
    }
}

// ---------------- weight transpose + split (single W) ----------------
__global__ void k_wsplit(const float* __restrict__ W, int K, int N,
                         __nv_bfloat16* __restrict__ out)
{
    int idx = blockIdx.x * blockDim.x + threadIdx.x;
    if (idx >= N * K) return;
    int n = idx / K, k = idx - n * K;
    float v = W[(size_t)k * N + n];
    __nv_bfloat16 h = __float2bfloat16(v);
    __nv_bfloat16 l = __float2bfloat16(v - __bfloat162float(h));
    int b = k >> 3, p = k & 7;
    size_t base = (size_t)n * 3 * K + (size_t)(3 * b) * 8 + p;
    out[base]      = h;
    out[base + 8]  = h;
    out[base + 16] = l;
}

// merged [Wl | Wr] -> out rows 0..255 from Wl, 256..511 from Wr (K = HID)
__global__ void k_wsplit2(const float* __restrict__ Wl, const float* __restrict__ Wr,
                          __nv_bfloat16* __restrict__ out)
{
    int idx = blockIdx.x * blockDim.x + threadIdx.x;
    if (idx >= 512 * HID) return;
    int n = idx / HID, k = idx - n * HID;
    const float* W = (n < 256) ? Wl : Wr;
    float v = W[(size_t)k * HID + (n & 255)];
    __nv_bfloat16 h = __float2bfloat16(v);
    __nv_bfloat16 l = __float2bfloat16(v - __bfloat162float(h));
    int b = k >> 3, p = k & 7;
    size_t base = (size_t)n * 3 * HID + (size_t)(3 * b) * 8 + p;
    out[base]      = h;
    out[base + 8]  = h;
    out[base + 16] = l;
}

// ---------------- CSR build ----------------
__global__ void k_csr_zero()
{
    int i = blockIdx.x * blockDim.x + threadIdx.x;
    if (i < N_NODES) g_cnt[i] = 0;
}
__global__ void k_csr_count(const int* __restrict__ ei)
{
    int e = blockIdx.x * blockDim.x + threadIdx.x;
    if (e >= E_TOT) return;
    int dst = (e < E_EDGES) ? ei[E_EDGES + e] : e - E_EDGES;
    atomicAdd(&g_cnt[dst], 1);
}
// single-block scan, warp-shuffle based
__global__ void __launch_bounds__(1024) k_csr_scan()
{
    __shared__ int wsum[32];
    __shared__ int stot;
    int tid = threadIdx.x, lane = tid & 31, wid = tid >> 5;
    int carry = 0;
    for (int base = 0; base < N_NODES; base += 1024) {
        int i = base + tid;
        int v = (i < N_NODES) ? g_cnt[i] : 0;
        int x = v;
#pragma unroll
        for (int o = 1; o < 32; o <<= 1) {
            int y = __shfl_up_sync(0xffffffffu, x, o);
            if (lane >= o) x += y;
        }
        if (lane == 31) wsum[wid] = x;
        __syncthreads();
        if (wid == 0) {
            int s = wsum[lane];
#pragma unroll
            for (int o = 1; o < 32; o <<= 1) {
                int y = __shfl_up_sync(0xffffffffu, s, o);
                if (lane >= o) s += y;
            }
            wsum[lane] = s;
            if (lane == 31) stot = s;
        }
        __syncthreads();
        int pre = (wid > 0) ? wsum[wid - 1] : 0;
        int excl = carry + pre + x - v;
        if (i < N_NODES) { g_off[i] = excl; g_cur[i] = excl; }
        carry += stot;
        __syncthreads();
    }
    if (tid == 0) g_off[N_NODES] = carry;
}
__global__ void k_csr_fill(const int* __restrict__ ei)
{
    int e = blockIdx.x * blockDim.x + threadIdx.x;
    if (e >= E_TOT) return;
    int src, dst;
    if (e < E_EDGES) { src = ei[e]; dst = ei[E_EDGES + e]; }
    else             { src = e - E_EDGES; dst = src; }
    int pos = atomicAdd(&g_cur[dst], 1);
    g_eid[pos]  = e;
    g_srcs[pos] = src;
}

// ---------------- fused per-layer attention, ONLINE softmax (warp per node) ----------
#define SCAP 128
template <int LAST>
__global__ void __launch_bounds__(256)
k_attn(const float* __restrict__ att, float* __restrict__ alphaOut,
       const float* __restrict__ bias, const float* __restrict__ clfW,
       const float* __restrict__ clfb, float* __restrict__ preds)
{
    __shared__ float4 sa[8][SCAP];
    int warp = (blockIdx.x * blockDim.x + threadIdx.x) >> 5;
    if (warp >= N_NODES) return;
    int lane = threadIdx.x & 31;
    int w = (threadIdx.x >> 5);
    int head = lane >> 3;
    int beg = g_off[warp];
    int deg = g_off[warp + 1] - beg;
    int base = lane * 8;
    float4* al4 = (float4*)alphaOut;
    float4* lg4 = (float4*)g_logits;
    const bool small = (deg <= SCAP);

    const float4* pr = (const float4*)(g_xr + (size_t)warp * HID + base);
    float4 r0 = pr[0], r1 = pr[1];
    const float4* pa = (const float4*)(att + base);
    float4 a0 = pa[0], a1 = pa[1];

    float m = -INFINITY, d = 0.f;
    float acc[8];
#pragma unroll
    for (int j = 0; j < 8; j++) acc[j] = 0.f;

    auto logit_of = [&](const float4& l0, const float4& l1) -> float {
        float sum, t;
        t = l0.x + r0.x; sum  = (t > 0.f ? t : 0.2f * t) * a0.x;
        t = l0.y + r0.y; sum += (t > 0.f ? t : 0.2f * t) * a0.y;
        t = l0.z + r0.z; sum += (t > 0.f ? t : 0.2f * t) * a0.z;
        t = l0.w + r0.w; sum += (t > 0.f ? t : 0.2f * t) * a0.w;
        t = l1.x + r1.x; sum += (t > 0.f ? t : 0.2f * t) * a1.x;
        t = l1.y + r1.y; sum += (t > 0.f ? t : 0.2f * t) * a1.y;
        t = l1.z + r1.z; sum += (t > 0.f ? t : 0.2f * t) * a1.z;
        t = l1.w + r1.w; sum += (t > 0.f ? t : 0.2f * t) * a1.w;
        return sum;
    };
    auto store_logit = [&](int i, float s) {
        if ((lane & 7) == 0) {
            if (small) ((float*)&sa[w][i])[head] = s;
            else       g_logits[(size_t)(beg + i) * NHEAD + head] = s;
        }
    };
    auto online = [&](float s, const float4& l0, const float4& l1) {
        if (s > m) {
            float c = __expf(m - s);
            d = d * c + 1.f;
            acc[0] = acc[0] * c + l0.x; acc[1] = acc[1] * c + l0.y;
            acc[2] = acc[2] * c + l0.z; acc[3] = acc[3] * c + l0.w;
            acc[4] = acc[4] * c + l1.x; acc[5] = acc[5] * c + l1.y;
            acc[6] = acc[6] * c + l1.z; acc[7] = acc[7] * c + l1.w;
            m = s;
        } else {
            float p = __expf(s - m);
            d += p;
            acc[0] += p * l0.x; acc[1] += p * l0.y;
            acc[2] += p * l0.z; acc[3] += p * l0.w;
            acc[4] += p * l1.x; acc[5] += p * l1.y;
            acc[6] += p * l1.z; acc[7] += p * l1.w;
        }
    };

    {
        int i = 0;
        for (; i + 1 < deg; i += 2) {
            int s0 = __ldg(&g_srcs[beg + i]);
            int s1 = __ldg(&g_srcs[beg + i + 1]);
            const float4* p0 = (const float4*)(g_xl + (size_t)s0 * HID + base);
            const float4* p1 = (const float4*)(g_xl + (size_t)s1 * HID + base);
            float4 u0 = p0[0], u1 = p0[1];
            float4 w0 = p1[0], w1 = p1[1];
            float su = logit_of(u0, u1);
            float sv = logit_of(w0, w1);
            su += __shfl_xor_sync(0xffffffffu, su, 4);
            sv += __shfl_xor_sync(0xffffffffu, sv, 4);
            su += __shfl_xor_sync(0xffffffffu, su, 2);
            sv += __shfl_xor_sync(0xffffffffu, sv, 2);
            su += __shfl_xor_sync(0xffffffffu, su, 1);
            sv += __shfl_xor_sync(0xffffffffu, sv, 1);
            store_logit(i, su);
            store_logit(i + 1, sv);
            online(su, u0, u1);
            online(sv, w0, w1);
        }
        if (i < deg) {
            int s0 = __ldg(&g_srcs[beg + i]);
            const float4* p0 = (const float4*)(g_xl + (size_t)s0 * HID + base);
            float4 u0 = p0[0], u1 = p0[1];
            float su = logit_of(u0, u1);
            su += __shfl_xor_sync(0xffffffffu, su, 4);
            su += __shfl_xor_sync(0xffffffffu, su, 2);
            su += __shfl_xor_sync(0xffffffffu, su, 1);
            store_logit(i, su);
            online(su, u0, u1);
        }
    }
    __syncwarp();

    float4 m4, d4;
    m4.x = __shfl_sync(0xffffffffu, m, 0);
    m4.y = __shfl_sync(0xffffffffu, m, 8);
    m4.z = __shfl_sync(0xffffffffu, m, 16);
    m4.w = __shfl_sync(0xffffffffu, m, 24);
    d4.x = __shfl_sync(0xffffffffu, d, 0);
    d4.y = __shfl_sync(0xffffffffu, d, 8);
    d4.z = __shfl_sync(0xffffffffu, d, 16);
    d4.w = __shfl_sync(0xffffffffu, d, 24);
    float4 inv4 = make_float4(1.f / (d4.x + 1e-16f), 1.f / (d4.y + 1e-16f),
                              1.f / (d4.z + 1e-16f), 1.f / (d4.w + 1e-16f));

    for (int i = lane; i < deg; i += 32) {
        float4 s4 = small ? sa[w][i] : lg4[beg + i];
        float4 a;
        a.x = __expf(s4.x - m4.x) * inv4.x;
        a.y = __expf(s4.y - m4.y) * inv4.y;
        a.z = __expf(s4.z - m4.z) * inv4.z;
        a.w = __expf(s4.w - m4.w) * inv4.w;
        al4[__ldg(&g_eid[beg + i])] = a;
    }

    float invd = 1.f / (d + 1e-16f);
    const float4* pb = (const float4*)(bias + base);
    float4 b0 = pb[0], b1 = pb[1];
    const float4* phv = (const float4*)(g_h + (size_t)warp * HID + base);
    float4 h0 = phv[0], h1 = phv[1];
    float v[8];
    v[0] = acc[0] * invd + b0.x + h0.x; v[1] = acc[1] * invd + b0.y + h0.y;
    v[2] = acc[2] * invd + b0.z + h0.z; v[3] = acc[3] * invd + b0.w + h0.w;
    v[4] = acc[4] * invd + b1.x + h1.x; v[5] = acc[5] * invd + b1.y + h1.y;
    v[6] = acc[6] * invd + b1.z + h1.z; v[7] = acc[7] * invd + b1.w + h1.w;
#pragma unroll
    for (int j = 0; j < 8; j++) v[j] = v[j] > 0.f ? v[j] : expm1f(v[j]);

    if (LAST == 0) {
        float4* po = (float4*)(g_h + (size_t)warp * HID + base);
        po[0] = make_float4(v[0], v[1], v[2], v[3]);
        po[1] = make_float4(v[4], v[5], v[6], v[7]);
        uint32_t hw[4], lw[4];
#pragma unroll
        for (int j = 0; j < 4; j++) {
            __nv_bfloat162 hb = __floats2bfloat162_rn(v[2 * j], v[2 * j + 1]);
            float lx = v[2 * j] - __low2float(hb);
            float ly = v[2 * j + 1] - __high2float(hb);
            __nv_bfloat162 lb = __floats2bfloat162_rn(lx, ly);
            memcpy(&hw[j], &hb, 4); memcpy(&lw[j], &lb, 4);
        }
        *(uint4*)(g_hhi + (size_t)warp * HID + base) = make_uint4(hw[0], hw[1], hw[2], hw[3]);
        *(uint4*)(g_hlo + (size_t)warp * HID + base) = make_uint4(lw[0], lw[1], lw[2], lw[3]);
    } else {
        const float4* pw = (const float4*)(clfW + base);
        float4 w0 = pw[0], w1 = pw[1];
        float s = v[0] * w0.x + v[1] * w0.y + v[2] * w0.z + v[3] * w0.w
                + v[4] * w1.x + v[5] * w1.y + v[6] * w1.z + v[7] * w1.w;
#pragma unroll
        for (int o = 16; o; o >>= 1) s += __shfl_xor_sync(0xffffffffu, s, o);
        if (lane == 0) preds[warp] = s + clfb[0];
    }
}

// ---------------- driver ----------------
extern "C" void kernel_launch(void* const* d_in, const int* in_sizes, int n_in,
                              void* d_out, int out_size)
{
    const float* x     = (const float*)d_in[0];
    const int*   ei    = (const int*)  d_in[1];
    const float* enc_W = (const float*)d_in[2];
    const float* enc_b = (const float*)d_in[3];
    const float* Wl0   = (const float*)d_in[4];
    const float* bl0   = (const float*)d_in[5];
    const float* Wr0   = (const float*)d_in[6];
    const float* br0   = (const float*)d_in[7];
    const float* att0  = (const float*)d_in[8];
    const float* bias0 = (const float*)d_in[9];
    const float* Wl1   = (const float*)d_in[10];
    const float* bl1   = (const float*)d_in[11];
    const float* Wr1   = (const float*)d_in[12];
    const float* br1   = (const float*)d_in[13];
    const float* att1  = (const float*)d_in[14];
    const float* bias1 = (const float*)d_in[15];
    const float* clf_W = (const float*)d_in[16];
    const float* clf_b = (const float*)d_in[17];

    float* out    = (float*)d_out;
    float* preds  = out;
    float* alpha0 = out + N_NODES;
    float* alpha1 = alpha0 + (size_t)E_TOT * NHEAD;

    float *ph, *pxl, *pxr;
    cudaGetSymbolAddress((void**)&ph,  g_h);
    cudaGetSymbolAddress((void**)&pxl, g_xl);
    cudaGetSymbolAddress((void**)&pxr, g_xr);
    __nv_bfloat16 *encT, *WT, *hhi, *hlo;
    cudaGetSymbolAddress((void**)&encT, g_encT);
    cudaGetSymbolAddress((void**)&WT,   g_WT);
    cudaGetSymbolAddress((void**)&hhi,  g_hhi);
    cudaGetSymbolAddress((void**)&hlo,  g_hlo);

    const int SMEM = 2 * STAGE_BYTES;   // 65536
    cudaFuncSetAttribute(gemm_tc, cudaFuncAttributeMaxDynamicSharedMemorySize, SMEM);

    const int LSTRIDE = 512 * HID * 3;
    const dim3 G_ENC(2, (N_NODES + 127) / 128);
    const dim3 G_LYR(4, (N_NODES + 127) / 128);

    // ncu (-s 5, 2 harness pre-launches) captures OUR index 3 = layer-0 gemm_tc
    k_wsplit<<<(HID * IN_DIM + 255) / 256, 256>>>(enc_W, IN_DIM, HID, encT);        // 0
    k_wsplit2<<<(512 * HID + 255) / 256, 256>>>(Wl0, Wr0, WT);                      // 1
    gemm_enc<<<G_ENC, 128>>>(x, encT, enc_b, ph, hhi, hlo, N_NODES, IN_DIM);        // 2
    gemm_tc<<<G_LYR, 128, SMEM>>>(hhi, hlo, WT, bl0, br0, pxl, pxr, N_NODES, HID);  // 3
    k_csr_zero<<<(N_NODES + 255) / 256, 256>>>();                                   // 4
    k_csr_count<<<(E_TOT + 255) / 256, 256>>>(ei);                                  // 5
    k_csr_scan<<<1, 1024>>>();                                                      // 6
    k_csr_fill<<<(E_TOT + 255) / 256, 256>>>(ei);                                   // 7
    k_attn<0><<<(N_NODES + 7) / 8, 256>>>(att0, alpha0, bias0,
                                          nullptr, nullptr, nullptr);               // 8
    k_wsplit2<<<(512 * HID + 255) / 256, 256>>>(Wl1, Wr1, WT + LSTRIDE);            // 9
    gemm_tc<<<G_LYR, 128, SMEM>>>(hhi, hlo, WT + LSTRIDE, bl1, br1, pxl, pxr,
                                  N_NODES, HID);                                    // 10
    k_attn<1><<<(N_NODES + 7) / 8, 256>>>(att1, alpha1, bias1, clf_W, clf_b, preds);// 11
}

// round 16
// speedup vs baseline: 1.0175x; 1.0175x over previous
#include <cuda_runtime.h>
#include <cuda_bf16.h>
#include <math.h>
#include <stdint.h>
#include <string.h>

#define N_NODES 50000
#define E_EDGES 800000
#define E_TOT   850000   // E + N self loops
#define IN_DIM  1280
#define HID     256
#define NHEAD   4
#define DHEAD   64

// ---------------- scratch (device globals: no allocation allowed) ----------------
__device__ float g_h[N_NODES * HID];
__device__ float g_xl[N_NODES * HID];
__device__ float g_xr[N_NODES * HID];
__device__ float g_logits[E_TOT * NHEAD];     // deg>SCAP fallback logit staging

// pre-split bf16 operands
__device__ __nv_bfloat16 g_xhi[N_NODES * IN_DIM];
__device__ __nv_bfloat16 g_xlo[N_NODES * IN_DIM];
__device__ __nv_bfloat16 g_hhi[N_NODES * HID];
__device__ __nv_bfloat16 g_hlo[N_NODES * HID];

// CSR (in-edges per destination node)
__device__ int g_cnt[N_NODES];
__device__ int g_off[N_NODES + 1];
__device__ int g_cur[N_NODES];
__device__ int g_eid[E_TOT];
__device__ int g_srcs[E_TOT];

// split weights, transposed to [N_out][3*K] bf16, role triplets per 8-k block:
// roles (B side): block 3b+0 = hi, 3b+1 = hi, 3b+2 = lo
__device__ __nv_bfloat16 g_encT[HID * IN_DIM * 3];
__device__ __nv_bfloat16 g_WT[2][512 * HID * 3];   // per layer: [Wl | Wr] merged

// ---------------- PTX helpers ----------------
__device__ __forceinline__ uint32_t smem_u32(const void* p) {
    uint32_t a;
    asm("{ .reg .u64 t; cvta.to.shared.u64 t, %1; cvt.u32.u64 %0, t; }" : "=r"(a) : "l"(p));
    return a;
}
__device__ __forceinline__ void ldsm_x4(uint32_t* r, uint32_t addr) {
    asm volatile("ldmatrix.sync.aligned.m8n8.x4.shared.b16 {%0,%1,%2,%3}, [%4];"
                 : "=r"(r[0]), "=r"(r[1]), "=r"(r[2]), "=r"(r[3]) : "r"(addr));
}
__device__ __forceinline__ void mma16816(float* c, const uint32_t* a, const uint32_t* b) {
    asm volatile("mma.sync.aligned.m16n8k16.row.col.f32.bf16.bf16.f32 "
                 "{%0,%1,%2,%3}, {%4,%5,%6,%7}, {%8,%9}, {%0,%1,%2,%3};"
                 : "+f"(c[0]), "+f"(c[1]), "+f"(c[2]), "+f"(c[3])
                 : "r"(a[0]), "r"(a[1]), "r"(a[2]), "r"(a[3]), "r"(b[0]), "r"(b[1]));
}
__device__ __forceinline__ void cp_async16(uint32_t dst, const void* src, int srcBytes) {
    asm volatile("cp.async.cg.shared.global [%0], [%1], 16, %2;"
                 :: "r"(dst), "l"(src), "r"(srcBytes) : "memory");
}
#define CP_COMMIT() asm volatile("cp.async.commit_group;" ::: "memory")
#define CP_WAIT1()  asm volatile("cp.async.wait_group 1;" ::: "memory")

// ============ unified GEMM (cp.async 3-stage, BK=32): C[M,Ncols] = A @ B'^T + bias ====
// 128 threads, 4 warps, CTA 128x128, warp 64x64. A pre-split Ahi/Alo bf16 [M][K].
// Role triplets: A (hi, lo, hi) x B (hi, hi, lo). Output col block <256 -> (Cl,biasL),
// else (Cr,biasR). SOUT=1 also writes bf16 hi/lo split of C (encoder feeding layers).
#define STAGE_BYTES 16384
template <int SOUT>
__global__ void __launch_bounds__(128, 2)
gemm_u(const __nv_bfloat16* __restrict__ Ahi, const __nv_bfloat16* __restrict__ Alo,
       const __nv_bfloat16* __restrict__ B,
       const float* __restrict__ biasL, const float* __restrict__ biasR,
       float* __restrict__ Cl, float* __restrict__ Cr,
       __nv_bfloat16* __restrict__ Chi, __nv_bfloat16* __restrict__ Clo,
       int M, int K)
{
    const int K2 = 3 * K;
    const int nCh = K2 >> 5;
    extern __shared__ __align__(16) char smbuf[];   // 3 * 16KB
    const uint32_t smbase = smem_u32(smbuf);

    const int tid  = threadIdx.x;
    const int lane = tid & 31;
    const int wid  = tid >> 5;
    const int mw   = wid & 1;
    const int nw   = wid >> 1;
    const int rowBase = blockIdx.y * 128;
    const int colBase = blockIdx.x * 128;

    float acc[4][8][4];
#pragma unroll
    for (int i = 0; i < 4; i++)
#pragma unroll
        for (int j = 0; j < 8; j++)
#pragma unroll
            for (int k = 0; k < 4; k++) acc[i][j][k] = 0.f;

    auto issue = [&](int ch) {
        if (ch < nCh) {
            uint32_t sa = smbase + (ch % 3) * STAGE_BYTES;
            uint32_t sb = sa + 8192;
#pragma unroll
            for (int i = 0; i < 4; i++) {
                int id = i * 128 + tid;
                int m = id >> 2, c = id & 3;
                int kb = ch * 4 + c;
                int b3 = kb / 3;
                int role = kb - 3 * b3;
                int rg = rowBase + m;
                int ok = (rg < M);
                const __nv_bfloat16* src = ((role == 1) ? Alo : Ahi)
                                         + (size_t)(ok ? rg : 0) * K + (b3 << 3);
                uint32_t off = m * 64 + ((c ^ ((m >> 1) & 3)) << 4);
                cp_async16(sa + off, src, ok ? 16 : 0);
            }
#pragma unroll
            for (int i = 0; i < 4; i++) {
                int id = i * 128 + tid;
                int n = id >> 2, c = id & 3;
                const __nv_bfloat16* src = B + (size_t)(colBase + n) * K2 + (ch << 5) + (c << 3);
                uint32_t off = n * 64 + ((c ^ ((n >> 1) & 3)) << 4);
                cp_async16(sb + off, src, 16);
            }
        }
        CP_COMMIT();
    };

    issue(0); issue(1);
    for (int ch = 0; ch < nCh; ch++) {
        CP_WAIT1();
        __syncthreads();
        issue(ch + 2);

        uint32_t sA = smbase + (ch % 3) * STAGE_BYTES;
        uint32_t sB = sA + 8192;
#pragma unroll
        for (int ks = 0; ks < 2; ks++) {
            uint32_t af[4][4], bf[4][4];
            int g = lane >> 3;
#pragma unroll
            for (int mt = 0; mt < 4; mt++) {
                int r = mw * 64 + mt * 16 + ((g & 1) << 3) + (lane & 7);
                int kb = ks * 2 + (g >> 1);
                ldsm_x4(af[mt], sA + r * 64 + ((kb ^ ((r >> 1) & 3)) << 4));
            }
#pragma unroll
            for (int p = 0; p < 4; p++) {
                int r = nw * 64 + p * 16 + (((g >> 1) & 1) << 3) + (lane & 7);
                int kb = ks * 2 + (g & 1);
                ldsm_x4(bf[p], sB + r * 64 + ((kb ^ ((r >> 1) & 3)) << 4));
            }
#pragma unroll
            for (int mt = 0; mt < 4; mt++)
#pragma unroll
                for (int nt = 0; nt < 8; nt++)
                    mma16816(acc[mt][nt], af[mt], &bf[nt >> 1][(nt & 1) * 2]);
        }
    }

    float* Cout = (colBase < 256) ? Cl : Cr;
    const float* bias = (colBase < 256) ? biasL : biasR;
    const int cb = colBase & 255;

#pragma unroll
    for (int mt = 0; mt < 4; mt++) {
        int m0 = rowBase + mw * 64 + mt * 16 + (lane >> 2);
#pragma unroll
        for (int half = 0; half < 2; half++) {
            int rg = m0 + half * 8;
            if (rg < M) {
                float* cp = Cout + (size_t)rg * 256;
#pragma unroll
                for (int nt = 0; nt < 8; nt++) {
                    int n0 = cb + nw * 64 + nt * 8 + (lane & 3) * 2;
                    float2 o;
                    o.x = acc[mt][nt][half * 2 + 0] + bias[n0];
                    o.y = acc[mt][nt][half * 2 + 1] + bias[n0 + 1];
                    *(float2*)(cp + n0) = o;
                    if (SOUT) {
                        __nv_bfloat162 hb = __floats2bfloat162_rn(o.x, o.y);
                        __nv_bfloat162 lb = __floats2bfloat162_rn(o.x - __low2float(hb),
                                                                  o.y - __high2float(hb));
                        *(__nv_bfloat162*)(Chi + (size_t)rg * 256 + n0) = hb;
                        *(__nv_bfloat162*)(Clo + (size_t)rg * 256 + n0) = lb;
                    }
                }
            }
        }
    }
}

// ---------------- x split: fp32 -> hi/lo bf16 ----------------
__global__ void k_xsplit(const float* __restrict__ x,
                         __nv_bfloat16* __restrict__ hi, __nv_bfloat16* __restrict__ lo,
                         int n4)
{
    int idx = blockIdx.x * blockDim.x + threadIdx.x;
    if (idx >= n4) return;
    float4 v = ((const float4*)x)[idx];
    __nv_bfloat162 h0 = __floats2bfloat162_rn(v.x, v.y);
    __nv_bfloat162 h1 = __floats2bfloat162_rn(v.z, v.w);
    __nv_bfloat162 l0 = __floats2bfloat162_rn(v.x - __low2float(h0), v.y - __high2float(h0));
    __nv_bfloat162 l1 = __floats2bfloat162_rn(v.z - __low2float(h1), v.w - __high2float(h1));
    ((__nv_bfloat162*)hi)[idx * 2]     = h0;
    ((__nv_bfloat162*)hi)[idx * 2 + 1] = h1;
    ((__nv_bfloat162*)lo)[idx * 2]     = l0;
    ((__nv_bfloat162*)lo)[idx * 2 + 1] = l1;
}

// ---------------- weight transpose + split (single W) ----------------
__global__ void k_wsplit(const float* __restrict__ W, int K, int N,
                         __nv_bfloat16* __restrict__ out)
{
    int idx = blockIdx.x * blockDim.x + threadIdx.x;
    if (idx >= N * K) return;
    int n = idx / K, k = idx - n * K;
    float v = W[(size_t)k * N + n];
    __nv_bfloat16 h = __float2bfloat16(v);
    __nv_bfloat16 l = __float2bfloat16(v - __bfloat162float(h));
    int b = k >> 3, p = k & 7;
    size_t base = (size_t)n * 3 * K + (size_t)(3 * b) * 8 + p;
    out[base]      = h;
    out[base + 8]  = h;
    out[base + 16] = l;
}

// merged [Wl | Wr] -> out rows 0..255 from Wl, 256..511 from Wr (K = HID)
__global__ void k_wsplit2(const float* __restrict__ Wl, const float* __restrict__ Wr,
                          __nv_bfloat16* __restrict__ out)
{
    int idx = blockIdx.x * blockDim.x + threadIdx.x;
    if (idx >= 512 * HID) return;
    int n = idx / HID, k = idx - n * HID;
    const float* W = (n < 256) ? Wl : Wr;
    float v = W[(size_t)k * HID + (n & 255)];
    __nv_bfloat16 h = __float2bfloat16(v);
    __nv_bfloat16 l = __float2bfloat16(v - __bfloat162float(h));
    int b = k >> 3, p = k & 7;
    size_t base = (size_t)n * 3 * HID + (size_t)(3 * b) * 8 + p;
    out[base]      = h;
    out[base + 8]  = h;
    out[base + 16] = l;
}

// ---------------- CSR build ----------------
__global__ void k_csr_zero()
{
    int i = blockIdx.x * blockDim.x + threadIdx.x;
    if (i < N_NODES) g_cnt[i] = 0;
}
__global__ void k_csr_count(const int* __restrict__ ei)
{
    int e = blockIdx.x * blockDim.x + threadIdx.x;
    if (e >= E_TOT) return;
    int dst = (e < E_EDGES) ? ei[E_EDGES + e] : e - E_EDGES;
    atomicAdd(&g_cnt[dst], 1);
}
// single-block scan, warp-shuffle based
__global__ void __launch_bounds__(1024) k_csr_scan()
{
    __shared__ int wsum[32];
    __shared__ int stot;
    int tid = threadIdx.x, lane = tid & 31, wid = tid >> 5;
    int carry = 0;
    for (int base = 0; base < N_NODES; base += 1024) {
        int i = base + tid;
        int v = (i < N_NODES) ? g_cnt[i] : 0;
        int x = v;
#pragma unroll
        for (int o = 1; o < 32; o <<= 1) {
            int y = __shfl_up_sync(0xffffffffu, x, o);
            if (lane >= o) x += y;
        }
        if (lane == 31) wsum[wid] = x;
        __syncthreads();
        if (wid == 0) {
            int s = wsum[lane];
#pragma unroll
            for (int o = 1; o < 32; o <<= 1) {
                int y = __shfl_up_sync(0xffffffffu, s, o);
                if (lane >= o) s += y;
            }
            wsum[lane] = s;
            if (lane == 31) stot = s;
        }
        __syncthreads();
        int pre = (wid > 0) ? wsum[wid - 1] : 0;
        int excl = carry + pre + x - v;
        if (i < N_NODES) { g_off[i] = excl; g_cur[i] = excl; }
        carry += stot;
        __syncthreads();
    }
    if (tid == 0) g_off[N_NODES] = carry;
}
__global__ void k_csr_fill(const int* __restrict__ ei)
{
    int e = blockIdx.x * blockDim.x + threadIdx.x;
    if (e >= E_TOT) return;
    int src, dst;
    if (e < E_EDGES) { src = ei[e]; dst = ei[E_EDGES + e]; }
    else             { src = e - E_EDGES; dst = src; }
    int pos = atomicAdd(&g_cur[dst], 1);
    g_eid[pos]  = e;
    g_srcs[pos] = src;
}

// ---------------- fused per-layer attention, ONLINE softmax (warp per node) ----------
#define SCAP 128
template <int LAST>
__global__ void __launch_bounds__(256)
k_attn(const float* __restrict__ att, float* __restrict__ alphaOut,
       const float* __restrict__ bias, const float* __restrict__ clfW,
       const float* __restrict__ clfb, float* __restrict__ preds)
{
    __shared__ float4 sa[8][SCAP];
    int warp = (blockIdx.x * blockDim.x + threadIdx.x) >> 5;
    if (warp >= N_NODES) return;
    int lane = threadIdx.x & 31;
    int w = (threadIdx.x >> 5);
    int head = lane >> 3;
    int beg = g_off[warp];
    int deg = g_off[warp + 1] - beg;
    int base = lane * 8;
    float4* al4 = (float4*)alphaOut;
    float4* lg4 = (float4*)g_logits;
    const bool small = (deg <= SCAP);

    const float4* pr = (const float4*)(g_xr + (size_t)warp * HID + base);
    float4 r0 = pr[0], r1 = pr[1];
    const float4* pa = (const float4*)(att + base);
    float4 a0 = pa[0], a1 = pa[1];

    float m = -INFINITY, d = 0.f;
    float acc[8];
#pragma unroll
    for (int j = 0; j < 8; j++) acc[j] = 0.f;

    auto logit_of = [&](const float4& l0, const float4& l1) -> float {
        float sum, t;
        t = l0.x + r0.x; sum  = (t > 0.f ? t : 0.2f * t) * a0.x;
        t = l0.y + r0.y; sum += (t > 0.f ? t : 0.2f * t) * a0.y;
        t = l0.z + r0.z; sum += (t > 0.f ? t : 0.2f * t) * a0.z;
        t = l0.w + r0.w; sum += (t > 0.f ? t : 0.2f * t) * a0.w;
        t = l1.x + r1.x; sum += (t > 0.f ? t : 0.2f * t) * a1.x;
        t = l1.y + r1.y; sum += (t > 0.f ? t : 0.2f * t) * a1.y;
        t = l1.z + r1.z; sum += (t > 0.f ? t : 0.2f * t) * a1.z;
        t = l1.w + r1.w; sum += (t > 0.f ? t : 0.2f * t) * a1.w;
        return sum;
    };
    auto store_logit = [&](int i, float s) {
        if ((lane & 7) == 0) {
            if (small) ((float*)&sa[w][i])[head] = s;
            else       g_logits[(size_t)(beg + i) * NHEAD + head] = s;
        }
    };
    auto online = [&](float s, const float4& l0, const float4& l1) {
        if (s > m) {
            float c = __expf(m - s);
            d = d * c + 1.f;
            acc[0] = acc[0] * c + l0.x; acc[1] = acc[1] * c + l0.y;
            acc[2] = acc[2] * c + l0.z; acc[3] = acc[3] * c + l0.w;
            acc[4] = acc[4] * c + l1.x; acc[5] = acc[5] * c + l1.y;
            acc[6] = acc[6] * c + l1.z; acc[7] = acc[7] * c + l1.w;
            m = s;
        } else {
            float p = __expf(s - m);
            d += p;
            acc[0] += p * l0.x; acc[1] += p * l0.y;
            acc[2] += p * l0.z; acc[3] += p * l0.w;
            acc[4] += p * l1.x; acc[5] += p * l1.y;
            acc[6] += p * l1.z; acc[7] += p * l1.w;
        }
    };

    {
        int i = 0;
        for (; i + 1 < deg; i += 2) {
            int s0 = __ldg(&g_srcs[beg + i]);
            int s1 = __ldg(&g_srcs[beg + i + 1]);
            const float4* p0 = (const float4*)(g_xl + (size_t)s0 * HID + base);
            const float4* p1 = (const float4*)(g_xl + (size_t)s1 * HID + base);
            float4 u0 = p0[0], u1 = p0[1];
            float4 w0 = p1[0], w1 = p1[1];
            float su = logit_of(u0, u1);
            float sv = logit_of(w0, w1);
            su += __shfl_xor_sync(0xffffffffu, su, 4);
            sv += __shfl_xor_sync(0xffffffffu, sv, 4);
            su += __shfl_xor_sync(0xffffffffu, su, 2);
            sv += __shfl_xor_sync(0xffffffffu, sv, 2);
            su += __shfl_xor_sync(0xffffffffu, su, 1);
            sv += __shfl_xor_sync(0xffffffffu, sv, 1);
            store_logit(i, su);
            store_logit(i + 1, sv);
            online(su, u0, u1);
            online(sv, w0, w1);
        }
        if (i < deg) {
            int s0 = __ldg(&g_srcs[beg + i]);
            const float4* p0 = (const float4*)(g_xl + (size_t)s0 * HID + base);
            float4 u0 = p0[0], u1 = p0[1];
            float su = logit_of(u0, u1);
            su += __shfl_xor_sync(0xffffffffu, su, 4);
            su += __shfl_xor_sync(0xffffffffu, su, 2);
            su += __shfl_xor_sync(0xffffffffu, su, 1);
            store_logit(i, su);
            online(su, u0, u1);
        }
    }
    __syncwarp();

    float4 m4, d4;
    m4.x = __shfl_sync(0xffffffffu, m, 0);
    m4.y = __shfl_sync(0xffffffffu, m, 8);
    m4.z = __shfl_sync(0xffffffffu, m, 16);
    m4.w = __shfl_sync(0xffffffffu, m, 24);
    d4.x = __shfl_sync(0xffffffffu, d, 0);
    d4.y = __shfl_sync(0xffffffffu, d, 8);
    d4.z = __shfl_sync(0xffffffffu, d, 16);
    d4.w = __shfl_sync(0xffffffffu, d, 24);
    float4 inv4 = make_float4(1.f / (d4.x + 1e-16f), 1.f / (d4.y + 1e-16f),
                              1.f / (d4.z + 1e-16f), 1.f / (d4.w + 1e-16f));

    for (int i = lane; i < deg; i += 32) {
        float4 s4 = small ? sa[w][i] : lg4[beg + i];
        float4 a;
        a.x = __expf(s4.x - m4.x) * inv4.x;
        a.y = __expf(s4.y - m4.y) * inv4.y;
        a.z = __expf(s4.z - m4.z) * inv4.z;
        a.w = __expf(s4.w - m4.w) * inv4.w;
        al4[__ldg(&g_eid[beg + i])] = a;
    }

    float invd = 1.f / (d + 1e-16f);
    const float4* pb = (const float4*)(bias + base);
    float4 b0 = pb[0], b1 = pb[1];
    const float4* phv = (const float4*)(g_h + (size_t)warp * HID + base);
    float4 h0 = phv[0], h1 = phv[1];
    float v[8];
    v[0] = acc[0] * invd + b0.x + h0.x; v[1] = acc[1] * invd + b0.y + h0.y;
    v[2] = acc[2] * invd + b0.z + h0.z; v[3] = acc[3] * invd + b0.w + h0.w;
    v[4] = acc[4] * invd + b1.x + h1.x; v[5] = acc[5] * invd + b1.y + h1.y;
    v[6] = acc[6] * invd + b1.z + h1.z; v[7] = acc[7] * invd + b1.w + h1.w;
#pragma unroll
    for (int j = 0; j < 8; j++) v[j] = v[j] > 0.f ? v[j] : expm1f(v[j]);

    if (LAST == 0) {
        float4* po = (float4*)(g_h + (size_t)warp * HID + base);
        po[0] = make_float4(v[0], v[1], v[2], v[3]);
        po[1] = make_float4(v[4], v[5], v[6], v[7]);
        uint32_t hw[4], lw[4];
#pragma unroll
        for (int j = 0; j < 4; j++) {
            __nv_bfloat162 hb = __floats2bfloat162_rn(v[2 * j], v[2 * j + 1]);
            float lx = v[2 * j] - __low2float(hb);
            float ly = v[2 * j + 1] - __high2float(hb);
            __nv_bfloat162 lb = __floats2bfloat162_rn(lx, ly);
            memcpy(&hw[j], &hb, 4); memcpy(&lw[j], &lb, 4);
        }
        *(uint4*)(g_hhi + (size_t)warp * HID + base) = make_uint4(hw[0], hw[1], hw[2], hw[3]);
        *(uint4*)(g_hlo + (size_t)warp * HID + base) = make_uint4(lw[0], lw[1], lw[2], lw[3]);
    } else {
        const float4* pw = (const float4*)(clfW + base);
        float4 w0 = pw[0], w1 = pw[1];
        float s = v[0] * w0.x + v[1] * w0.y + v[2] * w0.z + v[3] * w0.w
                + v[4] * w1.x + v[5] * w1.y + v[6] * w1.z + v[7] * w1.w;
#pragma unroll
        for (int o = 16; o; o >>= 1) s += __shfl_xor_sync(0xffffffffu, s, o);
        if (lane == 0) preds[warp] = s + clfb[0];
    }
}

// ---------------- driver ----------------
extern "C" void kernel_launch(void* const* d_in, const int* in_sizes, int n_in,
                              void* d_out, int out_size)
{
    const float* x     = (const float*)d_in[0];
    const int*   ei    = (const int*)  d_in[1];
    const float* enc_W = (const float*)d_in[2];
    const float* enc_b = (const float*)d_in[3];
    const float* Wl0   = (const float*)d_in[4];
    const float* bl0   = (const float*)d_in[5];
    const float* Wr0   = (const float*)d_in[6];
    const float* br0   = (const float*)d_in[7];
    const float* att0  = (const float*)d_in[8];
    const float* bias0 = (const float*)d_in[9];
    const float* Wl1   = (const float*)d_in[10];
    const float* bl1   = (const float*)d_in[11];
    const float* Wr1   = (const float*)d_in[12];
    const float* br1   = (const float*)d_in[13];
    const float* att1  = (const float*)d_in[14];
    const float* bias1 = (const float*)d_in[15];
    const float* clf_W = (const float*)d_in[16];
    const float* clf_b = (const float*)d_in[17];

    float* out    = (float*)d_out;
    float* preds  = out;
    float* alpha0 = out + N_NODES;
    float* alpha1 = alpha0 + (size_t)E_TOT * NHEAD;

    float *ph, *pxl, *pxr;
    cudaGetSymbolAddress((void**)&ph,  g_h);
    cudaGetSymbolAddress((void**)&pxl, g_xl);
    cudaGetSymbolAddress((void**)&pxr, g_xr);
    __nv_bfloat16 *encT, *WT, *xhi, *xlo, *hhi, *hlo;
    cudaGetSymbolAddress((void**)&encT, g_encT);
    cudaGetSymbolAddress((void**)&WT,   g_WT);
    cudaGetSymbolAddress((void**)&xhi,  g_xhi);
    cudaGetSymbolAddress((void**)&xlo,  g_xlo);
    cudaGetSymbolAddress((void**)&hhi,  g_hhi);
    cudaGetSymbolAddress((void**)&hlo,  g_hlo);

    const int SMEM = 3 * STAGE_BYTES;   // 49152
    cudaFuncSetAttribute(gemm_u<0>, cudaFuncAttributeMaxDynamicSharedMemorySize, SMEM);
    cudaFuncSetAttribute(gemm_u<1>, cudaFuncAttributeMaxDynamicSharedMemorySize, SMEM);

    const int LSTRIDE = 512 * HID * 3;
    const dim3 G_ENC(2, (N_NODES + 127) / 128);
    const dim3 G_LYR(4, (N_NODES + 127) / 128);

    // ncu (-s 5, 2 harness pre-launches) captures OUR index 3 = encoder gemm
    k_xsplit<<<(N_NODES * IN_DIM / 4 + 255) / 256, 256>>>(x, xhi, xlo,
                                                          N_NODES * IN_DIM / 4);    // 0
    k_wsplit<<<(HID * IN_DIM + 255) / 256, 256>>>(enc_W, IN_DIM, HID, encT);        // 1
    k_wsplit2<<<(512 * HID + 255) / 256, 256>>>(Wl0, Wr0, WT);                      // 2
    gemm_u<1><<<G_ENC, 128, SMEM>>>(xhi, xlo, encT, enc_b, enc_b, ph, ph,
                                    hhi, hlo, N_NODES, IN_DIM);                     // 3
    gemm_u<0><<<G_LYR, 128, SMEM>>>(hhi, hlo, WT, bl0, br0, pxl, pxr,
                                    nullptr, nullptr, N_NODES, HID);                // 4
    k_csr_zero<<<(N_NODES + 255) / 256, 256>>>();                                   // 5
    k_csr_count<<<(E_TOT + 255) / 256, 256>>>(ei);                                  // 6
    k_csr_scan<<<1, 1024>>>();                                                      // 7
    k_csr_fill<<<(E_TOT + 255) / 256, 256>>>(ei);                                   // 8
    k_attn<0><<<(N_NODES + 7) / 8, 256>>>(att0, alpha0, bias0,
                                          nullptr, nullptr, nullptr);               // 9
    k_wsplit2<<<(512 * HID + 255) / 256, 256>>>(Wl1, Wr1, WT + LSTRIDE);            // 10
    gemm_u<0><<<G_LYR, 128, SMEM>>>(hhi, hlo, WT + LSTRIDE, bl1, br1, pxl, pxr,
                                    nullptr, nullptr, N_NODES, HID);                // 11
    k_attn<1><<<(N_NODES + 7) / 8, 256>>>(att1, alpha1, bias1, clf_W, clf_b, preds);// 12
}